// round 10
// baseline (speedup 1.0000x reference)
#include <cuda_runtime.h>
#include <cuda_bf16.h>

// ---------------------------------------------------------------------------
// GaussianVoxelizer, single fused kernel, tile x gaussian-half split:
//   grid = (13,13,4): 8x8x4-voxel tiles x 2 gaussian splits.
//   Each block: stages its 512-gaussian half into smem (coalesced), culls
//   (sqrt-free squared tests, warp-private ballot compaction into
//   pair-interleaved records), evaluates packed f32x2 pairs, stores a partial.
//   Second-arriving block per tile (threadfence+atomic parity counter)
//   combines out = p0 + p1 (fixed order -> deterministic output).
//   Cull: 5-sigma per-axis (maha >= d^2/Sigma_ii => culled < exp(-12.5)).
//   Reference's exact 3-sigma vol mask applied in squared form.
// Fallback (non-regular grid): brute force.
// ---------------------------------------------------------------------------

#define SCHUNK 512                // gaussians staged/culled per chunk
#define SEG    (SCHUNK / 8)       // gaussians per warp segment (64)
#define SEGP   (SEG / 2)          // pairs per warp segment (32)
#define TSX 8
#define TSY 8
#define TSZ 4
#define CULL_K2 25.0f             // (5 sigma)^2
#define NVOX 80000
#define MAXTILES 512

__device__ float g_part[2][NVOX];
__device__ int g_ctr[MAXTILES];   // zero-init; parity-based, replay-safe

__device__ __forceinline__ float ex2_approx(float x) {
    float y;
    asm("ex2.approx.ftz.f32 %0, %1;" : "=f"(y) : "f"(x));
    return y;
}
__device__ __forceinline__ unsigned long long pack_x2(float lo, float hi) {
    unsigned long long r;
    asm("mov.b64 %0, {%1, %2};" : "=l"(r) : "f"(lo), "f"(hi));
    return r;
}
__device__ __forceinline__ void unpack_x2(unsigned long long v, float& lo, float& hi) {
    asm("mov.b64 {%0, %1}, %2;" : "=f"(lo), "=f"(hi) : "l"(v));
}
__device__ __forceinline__ unsigned long long add_x2(unsigned long long a, unsigned long long b) {
    unsigned long long d;
    asm("add.rn.f32x2 %0, %1, %2;" : "=l"(d) : "l"(a), "l"(b));
    return d;
}
__device__ __forceinline__ unsigned long long mul_x2(unsigned long long a, unsigned long long b) {
    unsigned long long d;
    asm("mul.rn.f32x2 %0, %1, %2;" : "=l"(d) : "l"(a), "l"(b));
    return d;
}
__device__ __forceinline__ unsigned long long fma_x2(unsigned long long a, unsigned long long b,
                                                     unsigned long long c) {
    unsigned long long d;
    asm("fma.rn.f32x2 %0, %1, %2, %3;" : "=l"(d) : "l"(a), "l"(b), "l"(c));
    return d;
}

__device__ __forceinline__ void eval_pair(
    const ulonglong2 r0, const ulonglong2 r1, const ulonglong2 r2,
    const ulonglong2 r3, const ulonglong2 r4,
    unsigned long long cxx, unsigned long long cyy, unsigned long long czz,
    float& acc) {
    unsigned long long dx = add_x2(cxx, r0.x);
    unsigned long long dy = add_x2(cyy, r0.y);
    unsigned long long dz = add_x2(czz, r1.x);
    unsigned long long t0 = fma_x2(r2.x, dx, fma_x2(r2.y, dy, mul_x2(r3.x, dz)));
    unsigned long long t1 = fma_x2(r3.y, dy, mul_x2(r4.x, dz));
    unsigned long long t2 = mul_x2(mul_x2(r4.y, dz), dz);
    unsigned long long ee = fma_x2(dx, t0, fma_x2(dy, t1, t2));
    float e0, e1, op0, op1;
    unpack_x2(ee, e0, e1);
    unpack_x2(r1.y, op0, op1);
    acc = fmaf(op0, ex2_approx(e0), acc);
    acc = fmaf(op1, ex2_approx(e1), acc);
}

__global__ __launch_bounds__(256) void gv_tile(
    const float* __restrict__ means,
    const float* __restrict__ ops,
    const float* __restrict__ covs,
    const float* __restrict__ vr,
    float* __restrict__ out,
    int G, int NX, int NY, int NZ) {
    __shared__ float s_means[3 * SCHUNK];            // 6 KB
    __shared__ float s_ops[SCHUNK];                  // 2 KB
    __shared__ float s_covs[9 * SCHUNK];             // 18 KB
    __shared__ ulonglong2 s_rec[(SCHUNK / 2) * 5];   // 20 KB pair records
    __shared__ int s_cnt[8];
    __shared__ int s_old;

    const int tid = threadIdx.x;
    const int lane = tid & 31;
    const int wid = tid >> 5;

    // tile / split decode: gridDim.z = ntz * 2
    const int tz = blockIdx.z >> 1;
    const int split = blockIdx.z & 1;
    const int tile = (tz * gridDim.y + blockIdx.y) * gridDim.x + blockIdx.x;

    const float v0 = vr[0], v1 = vr[1], v2 = vr[2];
    const float v3 = vr[3], v4 = vr[4], v5 = vr[5];
    const float voxx = (v3 - v0) / (float)NX;
    const float voxy = (v4 - v1) / (float)NY;
    const float voxz = (v5 - v2) / (float)NZ;

    // ---- analytic tile AABB (voxel centers, clamped) ----
    const int x0 = blockIdx.x * TSX, x1 = min(x0 + TSX - 1, NX - 1);
    const int y0 = blockIdx.y * TSY, y1 = min(y0 + TSY - 1, NY - 1);
    const int z0 = tz * TSZ,         z1 = min(z0 + TSZ - 1, NZ - 1);
    const float lox = v0 + ((float)x0 + 0.5f) * voxx;
    const float hix = v0 + ((float)x1 + 0.5f) * voxx;
    const float loy = v1 + ((float)y0 + 0.5f) * voxy;
    const float hiy = v1 + ((float)y1 + 0.5f) * voxy;
    const float loz = v2 + ((float)z0 + 0.5f) * voxz;
    const float hiz = v2 + ((float)z1 + 0.5f) * voxz;

    // ---- this thread's voxel ----
    const int X = x0 + (tid >> 5);
    const int Y = y0 + ((tid >> 2) & 7);
    const int Z = z0 + (tid & 3);
    const bool valid = (X < NX) && (Y < NY) && (Z < NZ);
    const int vidx = (X * NY + Y) * NZ + Z;
    const float cx = v0 + ((float)X + 0.5f) * voxx;
    const float cy = v1 + ((float)Y + 0.5f) * voxy;
    const float cz = v2 + ((float)Z + 0.5f) * voxz;
    const unsigned long long cxx = pack_x2(cx, cx);
    const unsigned long long cyy = pack_x2(cy, cy);
    const unsigned long long czz = pack_x2(cz, cz);

    // ---- this split's gaussian range ----
    const int Gh = (G + 1) >> 1;
    const int gLo = split * Gh;
    const int gHi = min(G, gLo + Gh);

    float acc0 = 0.0f, acc1 = 0.0f;
    float* frec = (float*)s_rec;

    for (int gbase = gLo; gbase < gHi; gbase += SCHUNK) {
        const int chunk = min(SCHUNK, gHi - gbase);

        // ---- coalesced stage of this chunk into smem ----
        for (int i = tid; i < 3 * chunk; i += 256) s_means[i] = means[3 * gbase + i];
        for (int i = tid; i < chunk; i += 256) s_ops[i] = ops[gbase + i];
        for (int i = tid; i < 9 * chunk; i += 256) s_covs[i] = covs[9 * gbase + i];
        __syncthreads();

        // ---- warp-private cull (sqrt-free) + pair-interleaved compaction ----
        const int wbase = wid * SEG;
        int wcount = 0;
#pragma unroll
        for (int p = 0; p < SEG; p += 32) {
            const int rel = wbase + p + lane;
            const bool inb = rel < chunk;

            float mx  = s_means[3 * rel + 0];
            float my  = s_means[3 * rel + 1];
            float mz  = s_means[3 * rel + 2];
            float op  = s_ops[rel];
            float caa = s_covs[9 * rel + 0];
            float cab = s_covs[9 * rel + 1];
            float cac = s_covs[9 * rel + 2];
            float cbb = s_covs[9 * rel + 4];
            float cbc = s_covs[9 * rel + 5];
            float ccc = s_covs[9 * rel + 8];

            // reference's 3-sigma vol mask, squared form: m+3s>v <=> v-m<0 || 9c>(v-m)^2
            float a0 = v0 - mx, a3 = mx - v3;
            float b1 = v1 - my, b4 = my - v4;
            float c2 = v2 - mz, c5 = mz - v5;
            bool mok = ((a0 < 0.f) | (9.f * caa > a0 * a0)) &
                       ((a3 < 0.f) | (9.f * caa > a3 * a3)) &
                       ((b1 < 0.f) | (9.f * cbb > b1 * b1)) &
                       ((b4 < 0.f) | (9.f * cbb > b4 * b4)) &
                       ((c2 < 0.f) | (9.f * ccc > c2 * c2)) &
                       ((c5 < 0.f) | (9.f * ccc > c5 * c5));
            // 5-sigma per-axis tile cull, squared form
            float gx = fmaxf(fmaxf(lox - mx, mx - hix), 0.0f);
            float gy = fmaxf(fmaxf(loy - my, my - hiy), 0.0f);
            float gz = fmaxf(fmaxf(loz - mz, mz - hiz), 0.0f);
            bool survive = inb && mok && (op != 0.0f) &&
                           (gx * gx <= CULL_K2 * caa) &&
                           (gy * gy <= CULL_K2 * cbb) &&
                           (gz * gz <= CULL_K2 * ccc);

            unsigned m = __ballot_sync(0xffffffffu, survive);
            if (survive) {
                const int pos = wbase + wcount + __popc(m & ((1u << lane) - 1u));
                // inverse of symmetric 3x3 (adjugate), -0.5*log2(e) folded
                float C00 = cbb * ccc - cbc * cbc;
                float C01 = cac * cbc - cab * ccc;
                float C02 = cab * cbc - cac * cbb;
                float C11 = caa * ccc - cac * cac;
                float C12 = cab * cac - caa * cbc;
                float C22 = caa * cbb - cab * cab;
                float det = caa * C00 + cab * C01 + cac * C02;
                float s = -0.72134752044448170f / det;
                float* f = frec + 20 * (pos >> 1) + (pos & 1);
                f[0]  = -mx;
                f[2]  = -my;
                f[4]  = -mz;
                f[6]  = op;
                f[8]  = s * C00;
                f[10] = 2.0f * s * C01;
                f[12] = 2.0f * s * C02;
                f[14] = s * C11;
                f[16] = 2.0f * s * C12;
                f[18] = s * C22;
            }
            wcount += __popc(m);
        }
        // pad odd count with a zero record (op=0, q=0 -> contributes exactly 0)
        if ((wcount & 1) && lane == 0) {
            float* f = frec + 20 * ((wbase + wcount) >> 1) + 1;
#pragma unroll
            for (int fi = 0; fi < 10; ++fi) f[2 * fi] = 0.0f;
        }
        if (lane == 0) s_cnt[wid] = wcount;
        __syncthreads();

        // ---- evaluate survivor pairs: 2-pair pipeline, dual accumulators ----
#pragma unroll
        for (int w = 0; w < 8; ++w) {
            const int np = (s_cnt[w] + 1) >> 1;
            const int pb = w * SEGP;
            int i = 0;
            for (; i + 2 <= np; i += 2) {
                const ulonglong2* Ra = &s_rec[5 * (pb + i)];
                const ulonglong2* Rb = &s_rec[5 * (pb + i + 1)];
                ulonglong2 a0 = Ra[0], a1 = Ra[1], a2 = Ra[2], a3 = Ra[3], a4 = Ra[4];
                ulonglong2 b0 = Rb[0], b1 = Rb[1], b2 = Rb[2], b3 = Rb[3], b4 = Rb[4];
                eval_pair(a0, a1, a2, a3, a4, cxx, cyy, czz, acc0);
                eval_pair(b0, b1, b2, b3, b4, cxx, cyy, czz, acc1);
            }
            if (i < np) {
                const ulonglong2* Ra = &s_rec[5 * (pb + i)];
                eval_pair(Ra[0], Ra[1], Ra[2], Ra[3], Ra[4], cxx, cyy, czz, acc0);
            }
        }
        __syncthreads();
    }

    // ---- partial store + second-arrival combine (deterministic order) ----
    if (valid) g_part[split][vidx] = acc0 + acc1;
    __threadfence();
    __syncthreads();
    if (tid == 0) s_old = atomicAdd(&g_ctr[tile], 1);
    __syncthreads();
    if (s_old & 1) {  // second arrival this launch (parity: replay-safe)
        if (valid) out[vidx] = g_part[0][vidx] + g_part[1][vidx];
    }
}

// Generic fallback: brute force over all gaussians per voxel (any layout).
__global__ __launch_bounds__(256) void gv_brute(
    const float* __restrict__ means,
    const float* __restrict__ ops,
    const float* __restrict__ covs,
    const float* __restrict__ coords,
    const float* __restrict__ vr,
    float* __restrict__ out,
    int G, int N) {
    __shared__ float4 s_a[SCHUNK];
    __shared__ float4 s_b[SCHUNK];
    __shared__ float2 s_c[SCHUNK];
    const int tid = threadIdx.x;
    const float v0 = vr[0], v1 = vr[1], v2 = vr[2];
    const float v3 = vr[3], v4 = vr[4], v5 = vr[5];
    int vidx = blockIdx.x * 256 + tid;
    bool valid = vidx < N;
    int li = valid ? vidx : 0;
    float cx = coords[3 * li + 0];
    float cy = coords[3 * li + 1];
    float cz = coords[3 * li + 2];
    float acc = 0.0f;
    for (int base = 0; base < G; base += SCHUNK) {
        int c = min(SCHUNK, G - base);
        for (int i = tid; i < c; i += 256) {
            int g = base + i;
            float mx = means[3 * g + 0];
            float my = means[3 * g + 1];
            float mz = means[3 * g + 2];
            float op = ops[g];
            float caa = covs[9 * g + 0];
            float cab = covs[9 * g + 1];
            float cac = covs[9 * g + 2];
            float cbb = covs[9 * g + 4];
            float cbc = covs[9 * g + 5];
            float ccc = covs[9 * g + 8];
            float sqa = sqrtf(caa), sqb = sqrtf(cbb), sqc = sqrtf(ccc);
            bool mask = (mx + 3.0f * sqa > v0) && (my + 3.0f * sqb > v1) &&
                        (mz + 3.0f * sqc > v2) && (mx - 3.0f * sqa < v3) &&
                        (my - 3.0f * sqb < v4) && (mz - 3.0f * sqc < v5);
            if (!mask) op = 0.0f;
            float C00 = cbb * ccc - cbc * cbc;
            float C01 = cac * cbc - cab * ccc;
            float C02 = cab * cbc - cac * cbb;
            float C11 = caa * ccc - cac * cac;
            float C12 = cab * cac - caa * cbc;
            float C22 = caa * cbb - cab * cab;
            float det = caa * C00 + cab * C01 + cac * C02;
            float s = -0.72134752044448170f / det;
            s_a[i] = make_float4(-mx, -my, -mz, op);
            s_b[i] = make_float4(s * C00, 2.0f * s * C01, 2.0f * s * C02,
                                 s * C11);
            s_c[i] = make_float2(2.0f * s * C12, s * C22);
        }
        __syncthreads();
        for (int i = 0; i < c; ++i) {
            float4 A = s_a[i];
            float4 B = s_b[i];
            float2 C = s_c[i];
            float dx = cx + A.x;
            float dy = cy + A.y;
            float dz = cz + A.z;
            float t0 = fmaf(B.x, dx, fmaf(B.y, dy, B.z * dz));
            float t1 = fmaf(B.w, dy, C.x * dz);
            float ee = fmaf(dx, t0, fmaf(dy, t1, (C.y * dz) * dz));
            acc = fmaf(A.w, ex2_approx(ee), acc);
        }
        __syncthreads();
    }
    if (valid) out[vidx] = acc;
}

extern "C" void kernel_launch(void* const* d_in, const int* in_sizes, int n_in,
                              void* d_out, int out_size) {
    const float* means  = (const float*)d_in[0];
    const float* ops    = (const float*)d_in[1];
    const float* covs   = (const float*)d_in[2];
    const float* coords = (const float*)d_in[3];
    const float* vr     = (const float*)d_in[4];
    float* out = (float*)d_out;

    int G = in_sizes[1];
    int N = in_sizes[3] / 3;

    const int NX = 100, NY = 100, NZ = 8;
    if (N == NX * NY * NZ) {
        dim3 grid((NX + TSX - 1) / TSX, (NY + TSY - 1) / TSY,
                  ((NZ + TSZ - 1) / TSZ) * 2);   // tiles x 2 gaussian splits
        gv_tile<<<grid, 256>>>(means, ops, covs, vr, out, G, NX, NY, NZ);
    } else {
        gv_brute<<<(N + 255) / 256, 256>>>(means, ops, covs, coords, vr, out,
                                           G, N);
    }
}

// round 11
// speedup vs baseline: 1.3114x; 1.3114x over previous
#include <cuda_runtime.h>
#include <cuda_bf16.h>

// ---------------------------------------------------------------------------
// GaussianVoxelizer, single fused kernel (regular-grid path):
//   grid = 8x8x2-voxel spatial tiles (13x13x4 = 676 blocks), 256 threads:
//   2 threads per voxel (survivor-segment halves).
//   Per block:
//     - analytic tile AABB from blockIdx (regular grid),
//     - 5-sigma per-axis cull (+ reference's exact 3-sigma vol mask),
//       loads + inversion hoisted before the ballot (full MLP),
//       warp-private compaction into pair-interleaved records,
//     - eval: half 0 evals segments 0-3, half 1 segments 4-7, packed f32x2
//       2-pair pipeline with dual accumulators,
//     - intra-block combine in fixed order (deterministic, no atomics).
//   Cull safety: maha >= d_i^2/Sigma_ii => culled weight < exp(-12.5)~3.7e-6.
// Fallback (non-regular grid): brute force, correctness only.
// ---------------------------------------------------------------------------

#define GCHUNK 1024
#define SEG    (GCHUNK / 8)       // gaussians per warp segment (128)
#define SEGP   (SEG / 2)          // pairs per warp segment (64)
#define TSX 8
#define TSY 8
#define TSZ 2
#define CULL_K 5.0f

__device__ __forceinline__ float ex2_approx(float x) {
    float y;
    asm("ex2.approx.ftz.f32 %0, %1;" : "=f"(y) : "f"(x));
    return y;
}
__device__ __forceinline__ unsigned long long pack_x2(float lo, float hi) {
    unsigned long long r;
    asm("mov.b64 %0, {%1, %2};" : "=l"(r) : "f"(lo), "f"(hi));
    return r;
}
__device__ __forceinline__ void unpack_x2(unsigned long long v, float& lo, float& hi) {
    asm("mov.b64 {%0, %1}, %2;" : "=f"(lo), "=f"(hi) : "l"(v));
}
__device__ __forceinline__ unsigned long long add_x2(unsigned long long a, unsigned long long b) {
    unsigned long long d;
    asm("add.rn.f32x2 %0, %1, %2;" : "=l"(d) : "l"(a), "l"(b));
    return d;
}
__device__ __forceinline__ unsigned long long mul_x2(unsigned long long a, unsigned long long b) {
    unsigned long long d;
    asm("mul.rn.f32x2 %0, %1, %2;" : "=l"(d) : "l"(a), "l"(b));
    return d;
}
__device__ __forceinline__ unsigned long long fma_x2(unsigned long long a, unsigned long long b,
                                                     unsigned long long c) {
    unsigned long long d;
    asm("fma.rn.f32x2 %0, %1, %2, %3;" : "=l"(d) : "l"(a), "l"(b), "l"(c));
    return d;
}

__device__ __forceinline__ void eval_pair(
    const ulonglong2 r0, const ulonglong2 r1, const ulonglong2 r2,
    const ulonglong2 r3, const ulonglong2 r4,
    unsigned long long cxx, unsigned long long cyy, unsigned long long czz,
    float& acc) {
    unsigned long long dx = add_x2(cxx, r0.x);
    unsigned long long dy = add_x2(cyy, r0.y);
    unsigned long long dz = add_x2(czz, r1.x);
    unsigned long long t0 = fma_x2(r2.x, dx, fma_x2(r2.y, dy, mul_x2(r3.x, dz)));
    unsigned long long t1 = fma_x2(r3.y, dy, mul_x2(r4.x, dz));
    unsigned long long t2 = mul_x2(mul_x2(r4.y, dz), dz);
    unsigned long long ee = fma_x2(dx, t0, fma_x2(dy, t1, t2));
    float e0, e1, op0, op1;
    unpack_x2(ee, e0, e1);
    unpack_x2(r1.y, op0, op1);
    acc = fmaf(op0, ex2_approx(e0), acc);
    acc = fmaf(op1, ex2_approx(e1), acc);
}

__global__ __launch_bounds__(256) void gv_tile(
    const float* __restrict__ means,
    const float* __restrict__ ops,
    const float* __restrict__ covs,
    const float* __restrict__ vr,
    float* __restrict__ out,
    int G, int NX, int NY, int NZ) {
    // Pair-interleaved survivor records: pair slot = 5 x ulonglong2 (80B).
    __shared__ ulonglong2 s_rec[(GCHUNK / 2) * 5];   // 40 KB
    __shared__ float s_red[TSX * TSY * TSZ];         // combine buffer
    __shared__ int s_cnt[8];

    const int tid = threadIdx.x;
    const int lane = tid & 31;
    const int wid = tid >> 5;
    const int vox = tid & 127;      // voxel within tile
    const int half = tid >> 7;      // survivor-segment half

    const float v0 = vr[0], v1 = vr[1], v2 = vr[2];
    const float v3 = vr[3], v4 = vr[4], v5 = vr[5];
    const float voxx = (v3 - v0) / (float)NX;
    const float voxy = (v4 - v1) / (float)NY;
    const float voxz = (v5 - v2) / (float)NZ;

    // ---- analytic tile AABB (voxel centers, clamped) ----
    const int x0 = blockIdx.x * TSX, x1 = min(x0 + TSX - 1, NX - 1);
    const int y0 = blockIdx.y * TSY, y1 = min(y0 + TSY - 1, NY - 1);
    const int z0 = blockIdx.z * TSZ, z1 = min(z0 + TSZ - 1, NZ - 1);
    const float lox = v0 + ((float)x0 + 0.5f) * voxx;
    const float hix = v0 + ((float)x1 + 0.5f) * voxx;
    const float loy = v1 + ((float)y0 + 0.5f) * voxy;
    const float hiy = v1 + ((float)y1 + 0.5f) * voxy;
    const float loz = v2 + ((float)z0 + 0.5f) * voxz;
    const float hiz = v2 + ((float)z1 + 0.5f) * voxz;

    // ---- this thread's voxel (vox: x = bits[4:7), y = bits[1:4), z = bit 0) ----
    const int X = x0 + (vox >> 4);
    const int Y = y0 + ((vox >> 1) & 7);
    const int Z = z0 + (vox & 1);
    const bool valid = (X < NX) && (Y < NY) && (Z < NZ);
    const float cx = v0 + ((float)X + 0.5f) * voxx;
    const float cy = v1 + ((float)Y + 0.5f) * voxy;
    const float cz = v2 + ((float)Z + 0.5f) * voxz;
    const unsigned long long cxx = pack_x2(cx, cx);
    const unsigned long long cyy = pack_x2(cy, cy);
    const unsigned long long czz = pack_x2(cz, cz);

    float acc0 = 0.0f, acc1 = 0.0f;
    float* frec = (float*)s_rec;

    for (int gbase = 0; gbase < G; gbase += GCHUNK) {
        const int chunk = min(GCHUNK, G - gbase);

        // ---- warp-private cull + pair-interleaved compaction ----
        const int wbase = wid * SEG;
        int wcount = 0;
#pragma unroll
        for (int p = 0; p < SEG; p += 32) {
            const int rel = wbase + p + lane;
            const bool inb = rel < chunk;
            const int g = gbase + (inb ? rel : 0);

            // unconditional clamped loads -> full MLP batch
            float mx  = means[3 * g + 0];
            float my  = means[3 * g + 1];
            float mz  = means[3 * g + 2];
            float op  = ops[g];
            float caa = covs[9 * g + 0];
            float cab = covs[9 * g + 1];
            float cac = covs[9 * g + 2];
            float cbb = covs[9 * g + 4];
            float cbc = covs[9 * g + 5];
            float ccc = covs[9 * g + 8];

            float sqa = sqrtf(caa), sqb = sqrtf(cbb), sqc = sqrtf(ccc);
            // reference's 3-sigma volume-range mask (exact form)
            bool mask = (mx + 3.0f * sqa > v0) && (my + 3.0f * sqb > v1) &&
                        (mz + 3.0f * sqc > v2) && (mx - 3.0f * sqa < v3) &&
                        (my - 3.0f * sqb < v4) && (mz - 3.0f * sqc < v5);
            // 5-sigma per-axis tile cull
            float gx = fmaxf(fmaxf(lox - mx, mx - hix), 0.0f);
            float gy = fmaxf(fmaxf(loy - my, my - hiy), 0.0f);
            float gz = fmaxf(fmaxf(loz - mz, mz - hiz), 0.0f);
            bool survive = inb && mask && (op != 0.0f) &&
                           (gx <= CULL_K * sqa) && (gy <= CULL_K * sqb) &&
                           (gz <= CULL_K * sqc);

            // inversion hoisted (cheap math; wasted for dead lanes)
            float C00 = cbb * ccc - cbc * cbc;
            float C01 = cac * cbc - cab * ccc;
            float C02 = cab * cbc - cac * cbb;
            float C11 = caa * ccc - cac * cac;
            float C12 = cab * cac - caa * cbc;
            float C22 = caa * cbb - cab * cab;
            float det = caa * C00 + cab * C01 + cac * C02;
            float s = -0.72134752044448170f / det;

            unsigned m = __ballot_sync(0xffffffffu, survive);
            if (survive) {
                const int pos = wbase + wcount + __popc(m & ((1u << lane) - 1u));
                float* f = frec + 20 * (pos >> 1) + (pos & 1);
                f[0]  = -mx;
                f[2]  = -my;
                f[4]  = -mz;
                f[6]  = op;
                f[8]  = s * C00;
                f[10] = 2.0f * s * C01;
                f[12] = 2.0f * s * C02;
                f[14] = s * C11;
                f[16] = 2.0f * s * C12;
                f[18] = s * C22;
            }
            wcount += __popc(m);
        }
        // pad odd count with a zero record (op=0, q=0 -> contributes exactly 0)
        if ((wcount & 1) && lane == 0) {
            float* f = frec + 20 * ((wbase + wcount) >> 1) + 1;
#pragma unroll
            for (int fi = 0; fi < 10; ++fi) f[2 * fi] = 0.0f;
        }
        if (lane == 0) s_cnt[wid] = wcount;
        __syncthreads();

        // ---- evaluate survivor pairs: this half's 4 segments ----
#pragma unroll
        for (int w4 = 0; w4 < 4; ++w4) {
            const int w = half * 4 + w4;
            const int np = (s_cnt[w] + 1) >> 1;
            const int pb = w * SEGP;
            int i = 0;
            for (; i + 2 <= np; i += 2) {
                const ulonglong2* Ra = &s_rec[5 * (pb + i)];
                const ulonglong2* Rb = &s_rec[5 * (pb + i + 1)];
                ulonglong2 a0 = Ra[0], a1 = Ra[1], a2 = Ra[2], a3 = Ra[3], a4 = Ra[4];
                ulonglong2 b0 = Rb[0], b1 = Rb[1], b2 = Rb[2], b3 = Rb[3], b4 = Rb[4];
                eval_pair(a0, a1, a2, a3, a4, cxx, cyy, czz, acc0);
                eval_pair(b0, b1, b2, b3, b4, cxx, cyy, czz, acc1);
            }
            if (i < np) {
                const ulonglong2* Ra = &s_rec[5 * (pb + i)];
                eval_pair(Ra[0], Ra[1], Ra[2], Ra[3], Ra[4], cxx, cyy, czz, acc0);
            }
        }
        __syncthreads();
    }

    // ---- intra-block combine, fixed order (deterministic) ----
    if (half == 1) s_red[vox] = acc0 + acc1;
    __syncthreads();
    if (half == 0 && valid)
        out[(X * NY + Y) * NZ + Z] = (acc0 + acc1) + s_red[vox];
}

// Generic fallback: brute force over all gaussians per voxel (any layout).
__global__ __launch_bounds__(256) void gv_brute(
    const float* __restrict__ means,
    const float* __restrict__ ops,
    const float* __restrict__ covs,
    const float* __restrict__ coords,
    const float* __restrict__ vr,
    float* __restrict__ out,
    int G, int N) {
    __shared__ float4 s_a[GCHUNK];
    __shared__ float4 s_b[GCHUNK];
    __shared__ float2 s_c[GCHUNK];
    const int tid = threadIdx.x;
    const float v0 = vr[0], v1 = vr[1], v2 = vr[2];
    const float v3 = vr[3], v4 = vr[4], v5 = vr[5];
    int vidx = blockIdx.x * 256 + tid;
    bool valid = vidx < N;
    int li = valid ? vidx : 0;
    float cx = coords[3 * li + 0];
    float cy = coords[3 * li + 1];
    float cz = coords[3 * li + 2];
    float acc = 0.0f;
    for (int base = 0; base < G; base += GCHUNK) {
        int c = min(GCHUNK, G - base);
        for (int i = tid; i < c; i += 256) {
            int g = base + i;
            float mx = means[3 * g + 0];
            float my = means[3 * g + 1];
            float mz = means[3 * g + 2];
            float op = ops[g];
            float caa = covs[9 * g + 0];
            float cab = covs[9 * g + 1];
            float cac = covs[9 * g + 2];
            float cbb = covs[9 * g + 4];
            float cbc = covs[9 * g + 5];
            float ccc = covs[9 * g + 8];
            float sqa = sqrtf(caa), sqb = sqrtf(cbb), sqc = sqrtf(ccc);
            bool mask = (mx + 3.0f * sqa > v0) && (my + 3.0f * sqb > v1) &&
                        (mz + 3.0f * sqc > v2) && (mx - 3.0f * sqa < v3) &&
                        (my - 3.0f * sqb < v4) && (mz - 3.0f * sqc < v5);
            if (!mask) op = 0.0f;
            float C00 = cbb * ccc - cbc * cbc;
            float C01 = cac * cbc - cab * ccc;
            float C02 = cab * cbc - cac * cbb;
            float C11 = caa * ccc - cac * cac;
            float C12 = cab * cac - caa * cbc;
            float C22 = caa * cbb - cab * cab;
            float det = caa * C00 + cab * C01 + cac * C02;
            float s = -0.72134752044448170f / det;
            s_a[i] = make_float4(-mx, -my, -mz, op);
            s_b[i] = make_float4(s * C00, 2.0f * s * C01, 2.0f * s * C02,
                                 s * C11);
            s_c[i] = make_float2(2.0f * s * C12, s * C22);
        }
        __syncthreads();
        for (int i = 0; i < c; ++i) {
            float4 A = s_a[i];
            float4 B = s_b[i];
            float2 C = s_c[i];
            float dx = cx + A.x;
            float dy = cy + A.y;
            float dz = cz + A.z;
            float t0 = fmaf(B.x, dx, fmaf(B.y, dy, B.z * dz));
            float t1 = fmaf(B.w, dy, C.x * dz);
            float ee = fmaf(dx, t0, fmaf(dy, t1, (C.y * dz) * dz));
            acc = fmaf(A.w, ex2_approx(ee), acc);
        }
        __syncthreads();
    }
    if (valid) out[vidx] = acc;
}

extern "C" void kernel_launch(void* const* d_in, const int* in_sizes, int n_in,
                              void* d_out, int out_size) {
    const float* means  = (const float*)d_in[0];
    const float* ops    = (const float*)d_in[1];
    const float* covs   = (const float*)d_in[2];
    const float* coords = (const float*)d_in[3];
    const float* vr     = (const float*)d_in[4];
    float* out = (float*)d_out;

    int G = in_sizes[1];
    int N = in_sizes[3] / 3;

    const int NX = 100, NY = 100, NZ = 8;
    if (N == NX * NY * NZ) {
        dim3 tiles((NX + TSX - 1) / TSX, (NY + TSY - 1) / TSY,
                   (NZ + TSZ - 1) / TSZ);
        gv_tile<<<tiles, 256>>>(means, ops, covs, vr, out, G, NX, NY, NZ);
    } else {
        gv_brute<<<(N + 255) / 256, 256>>>(means, ops, covs, coords, vr, out,
                                           G, N);
    }
}